// round 15
// baseline (speedup 1.0000x reference)
#include <cuda_runtime.h>
#include <cuda_fp16.h>
#include <stdint.h>

#define MAX_N  500000
#define MAX_NQ 500000
#define TILE   128            // nodes per main-kernel block (power of 2: nl = j & 127)
#define ROWB   272            // smem bytes per node row: 256 data + 16 pad (bank step 68%32=4)
#define MAX_TILES ((MAX_N + TILE - 1) / TILE)   // 3907
#define NSUB   4              // sub-buckets per tile (atomic contention / 4)
#define SUBCAP 128            // capacity per sub-bucket (expected ~32, max ~60)
#define CAP    (NSUB * SUBCAP)

__device__ unsigned g_tcursor[MAX_TILES * NSUB];        // zero-init; re-zeroed by main_k
__device__ unsigned g_bucket[(size_t)MAX_TILES * CAP];  // (query_i << 7) | (node & 127)

// ---- K1: single-pass bucket append with 4-way sub-counter spreading ----
__global__ void append_k(const int* __restrict__ k_idx, int nq) {
    int i = blockIdx.x * blockDim.x + threadIdx.x;
    if (i < nq) {
        int j   = k_idx[i];
        int b   = j >> 7;                     // tile id
        int sub = threadIdx.x & (NSUB - 1);
        unsigned pos = atomicAdd(&g_tcursor[b * NSUB + sub], 1u);
        if (pos < SUBCAP)
            g_bucket[(size_t)b * CAP + sub * SUBCAP + pos] =
                ((unsigned)i << 7) | (unsigned)(j & (TILE - 1));
    }
}

// ---- K2: main fused kernel ----
__global__ __launch_bounds__(256, 6) void main_k(
    const float* __restrict__ q_phi,     // [nq, 64]
    const float* __restrict__ pos,       // [64, N]
    const float* __restrict__ neg,       // [64, N]
    const float* __restrict__ deg_pos,   // [N, 8]
    const float* __restrict__ deg_neg,   // [N, 8]
    float* __restrict__ out,             // [2*nq*8]
    int N, int nq)
{
    __shared__ __align__(16) char sh[TILE * ROWB];   // node-major fp16, 34.0 KB
    const int n0  = blockIdx.x * TILE;
    const int tid = threadIdx.x;

    // ---- Phase 1: load phi slice, store node-major fp16 ----
    // Task = (group g 0..15, node nl 0..127). g<8: pos channels g*8..g*8+7, g>=8: neg.
    #pragma unroll
    for (int it = 0; it < 8; ++it) {
        int idx  = it * 256 + tid;           // 0..2047
        int lane = idx & 31;
        int nl32 = (idx >> 5) & 3;
        int g    = idx >> 7;                 // 0..15
        int nl   = nl32 * 32 + lane;
        int n    = n0 + nl;
        const float* src = (g < 8) ? (pos + (size_t)(g * 8) * N)
                                   : (neg + (size_t)((g - 8) * 8) * N);
        float f[8];
        #pragma unroll
        for (int kk = 0; kk < 8; ++kk)
            f[kk] = (n < N) ? src[(size_t)kk * N + n] : 0.f;

        __half2 h0 = __floats2half2_rn(f[0], f[1]);
        __half2 h1 = __floats2half2_rn(f[2], f[3]);
        __half2 h2 = __floats2half2_rn(f[4], f[5]);
        __half2 h3 = __floats2half2_rn(f[6], f[7]);
        uint4 w;
        w.x = *reinterpret_cast<uint32_t*>(&h0);
        w.y = *reinterpret_cast<uint32_t*>(&h1);
        w.z = *reinterpret_cast<uint32_t*>(&h2);
        w.w = *reinterpret_cast<uint32_t*>(&h3);
        *reinterpret_cast<uint4*>(sh + nl * ROWB + g * 16) = w;
    }
    __syncthreads();

    // ---- Phase 2: serve this tile's 4 sub-buckets ----
    unsigned c0 = g_tcursor[blockIdx.x * NSUB + 0]; if (c0 > SUBCAP) c0 = SUBCAP;
    unsigned c1 = g_tcursor[blockIdx.x * NSUB + 1]; if (c1 > SUBCAP) c1 = SUBCAP;
    unsigned c2 = g_tcursor[blockIdx.x * NSUB + 2]; if (c2 > SUBCAP) c2 = SUBCAP;
    unsigned c3 = g_tcursor[blockIdx.x * NSUB + 3]; if (c3 > SUBCAP) c3 = SUBCAP;
    unsigned t0 = c0, t1 = c0 + c1, t2 = t1 + c2, tot = t2 + c3;

    const unsigned* bucket = &g_bucket[(size_t)blockIdx.x * CAP];
    const size_t total = (size_t)nq * 8;

    for (unsigned s8 = tid; s8 < tot * 8u; s8 += 256u) {
        unsigned task = s8 >> 3;
        unsigned off;
        if      (task < t0) off = task;
        else if (task < t1) off = 1 * SUBCAP + (task - t0);
        else if (task < t2) off = 2 * SUBCAP + (task - t1);
        else                off = 3 * SUBCAP + (task - t2);
        unsigned srec = bucket[off];

        int h  = (int)(s8 & 7u);
        int i  = (int)(srec >> 7);
        int nl = (int)(srec & (TILE - 1));
        int j  = n0 + nl;

        const float4* qp = reinterpret_cast<const float4*>(q_phi + (size_t)i * 64 + h * 8);
        float4 q0 = qp[0];
        float4 q1 = qp[1];

        uint4 pw = *reinterpret_cast<const uint4*>(sh + nl * ROWB + h * 16);
        uint4 nw = *reinterpret_cast<const uint4*>(sh + nl * ROWB + 128 + h * 16);

        float2 p0 = __half22float2(*reinterpret_cast<__half2*>(&pw.x));
        float2 p1 = __half22float2(*reinterpret_cast<__half2*>(&pw.y));
        float2 p2 = __half22float2(*reinterpret_cast<__half2*>(&pw.z));
        float2 p3 = __half22float2(*reinterpret_cast<__half2*>(&pw.w));
        float2 m0 = __half22float2(*reinterpret_cast<__half2*>(&nw.x));
        float2 m1 = __half22float2(*reinterpret_cast<__half2*>(&nw.y));
        float2 m2 = __half22float2(*reinterpret_cast<__half2*>(&nw.z));
        float2 m3 = __half22float2(*reinterpret_cast<__half2*>(&nw.w));

        float dp = q0.x * p0.x + q0.y * p0.y + q0.z * p1.x + q0.w * p1.y
                 + q1.x * p2.x + q1.y * p2.y + q1.z * p3.x + q1.w * p3.y;
        float dn = q0.x * m0.x + q0.y * m0.y + q0.z * m1.x + q0.w * m1.y
                 + q1.x * m2.x + q1.y * m2.y + q1.z * m3.x + q1.w * m3.y;

        float denp = fmaxf(__ldg(deg_pos + (size_t)j * 8 + h), 1.0f);
        float denn = fmaxf(__ldg(deg_neg + (size_t)j * 8 + h), 1.0f);

        out[(size_t)i * 8 + h]         = dp / denp;
        out[total + (size_t)i * 8 + h] = dn / denn;
    }

    // ---- Phase 3: re-zero this tile's cursors for the next replay ----
    if (tid == 0)
        *reinterpret_cast<uint4*>(&g_tcursor[blockIdx.x * NSUB]) = make_uint4(0u, 0u, 0u, 0u);
}

// ---------------------------------------------------------------------------
extern "C" void kernel_launch(void* const* d_in, const int* in_sizes, int n_in,
                              void* d_out, int out_size)
{
    const float* q_phi   = (const float*)d_in[0];
    const float* phi_pos = (const float*)d_in[1];
    const float* phi_neg = (const float*)d_in[2];
    const float* deg_pos = (const float*)d_in[3];
    const float* deg_neg = (const float*)d_in[4];
    const int*   k_idx   = (const int*)d_in[5];

    int nq = in_sizes[0] / 64;
    int N  = in_sizes[1] / 64;
    if (N  > MAX_N)  N  = MAX_N;
    if (nq > MAX_NQ) nq = MAX_NQ;

    append_k<<<(nq + 255) / 256, 256>>>(k_idx, nq);

    int mblocks = (N + TILE - 1) / TILE;
    main_k<<<mblocks, 256>>>(q_phi, phi_pos, phi_neg, deg_pos, deg_neg,
                             (float*)d_out, N, nq);
}